// round 4
// baseline (speedup 1.0000x reference)
#include <cuda_runtime.h>
#include <cuda_bf16.h>
#include <stdint.h>
#include <math.h>

// ---------------------------------------------------------------- constants
constexpr int CB = 32, CS = 512, CD = 512;
constexpr int CSP = CS + 4;
constexpr int CIN = 3 * CD;          // 1536
constexpr int CM  = CB * CS;         // 16384
constexpr int NOUT = CM * 2 * CD;

// ------------------------------------------------- device scratch (no alloc)
__device__ __nv_bfloat16 g_padH[(size_t)CB * CSP * CD];
__device__ __nv_bfloat16 g_padL[(size_t)CB * CSP * CD];
__device__ __nv_bfloat16 g_pWH[(size_t)2 * CD * CIN];
__device__ __nv_bfloat16 g_pWL[(size_t)2 * CD * CIN];
__device__ __nv_bfloat16 g_hWH[(size_t)2 * 2 * 1024 * CD];
__device__ __nv_bfloat16 g_hWL[(size_t)2 * 2 * 1024 * CD];
__device__ __nv_bfloat16 g_a0H[(size_t)2 * CM * CD];
__device__ __nv_bfloat16 g_a0L[(size_t)2 * CM * CD];
__device__ __nv_bfloat16 g_a1H[(size_t)2 * CM * CD];
__device__ __nv_bfloat16 g_a1L[(size_t)2 * CM * CD];

// SMEM tile geometry: rows of 32 bf16 padded to 80 B (conflict-free ldmatrix)
constexpr uint32_t ROWB  = 80;
constexpr uint32_t TERM  = 128 * ROWB;       // 10240 B per term tile
constexpr uint32_t STAGE = 4 * TERM;         // Ah|Al|Bh|Bl = 40960 B
constexpr int      NSTG  = 3;
constexpr uint32_t SMEM_SZ = NSTG * STAGE;   // 122880 B (>= 67584 epilogue)

// ---------------------------------------------------------------- PTX utils
__device__ __forceinline__ uint32_t s2u(const void* p) {
    return (uint32_t)__cvta_generic_to_shared(p);
}
__device__ __forceinline__ void cpa16(uint32_t dst, const void* src) {
    asm volatile("cp.async.cg.shared.global [%0], [%1], 16;" :: "r"(dst), "l"(src));
}
__device__ __forceinline__ void ldsm4(uint32_t& r0, uint32_t& r1, uint32_t& r2,
                                      uint32_t& r3, uint32_t addr) {
    asm volatile("ldmatrix.sync.aligned.m8n8.x4.shared.b16 {%0,%1,%2,%3}, [%4];"
                 : "=r"(r0), "=r"(r1), "=r"(r2), "=r"(r3) : "r"(addr));
}
__device__ __forceinline__ void mma16816(float* d, const uint32_t* a, const uint32_t* b) {
    asm volatile(
        "mma.sync.aligned.m16n8k16.row.col.f32.bf16.bf16.f32 "
        "{%0,%1,%2,%3}, {%4,%5,%6,%7}, {%8,%9}, {%0,%1,%2,%3};"
        : "+f"(d[0]), "+f"(d[1]), "+f"(d[2]), "+f"(d[3])
        : "r"(a[0]), "r"(a[1]), "r"(a[2]), "r"(a[3]), "r"(b[0]), "r"(b[1]));
}
__device__ __forceinline__ void split2(float x, unsigned short& h, unsigned short& l) {
    __nv_bfloat16 hb = __float2bfloat16(x);
    __nv_bfloat16 lb = __float2bfloat16(x - __bfloat162float(hb));
    h = __bfloat16_as_ushort(hb);
    l = __bfloat16_as_ushort(lb);
}
__device__ __forceinline__ float bf2sum(unsigned short h, unsigned short l) {
    return __bfloat162float(__ushort_as_bfloat16(h)) +
           __bfloat162float(__ushort_as_bfloat16(l));
}

// ---------------------------------------------------------------- kernel 1
__global__ void pad_cvt(const float* __restrict__ inp, const float* __restrict__ lp,
                        const float* __restrict__ rp) {
    int idx = blockIdx.x * blockDim.x + threadIdx.x;   // float4 units
    const int per_b = CSP * (CD / 4);
    if (idx >= CB * per_b) return;
    int b = idx / per_b, rem = idx - b * per_b;
    int row = rem >> 7, d4 = rem & 127;
    float4 v;
    if (row < 2)             v = ((const float4*)lp)[row * 128 + d4];
    else if (row >= CSP - 2) v = ((const float4*)rp)[(row - (CSP - 2)) * 128 + d4];
    else v = ((const float4*)inp)[((size_t)b * CS + (row - 2)) * 128 + d4];
    ushort4 hv, lv;
    split2(v.x, hv.x, lv.x); split2(v.y, hv.y, lv.y);
    split2(v.z, hv.z, lv.z); split2(v.w, hv.w, lv.w);
    ((ushort4*)g_padH)[idx] = hv;
    ((ushort4*)g_padL)[idx] = lv;
}

// ---------------------------------------------------------------- kernel 2
__global__ void wcvt(const float* __restrict__ lW, const float* __restrict__ rW,
                     const float* __restrict__ lhw, const float* __restrict__ rhw) {
    int i4 = blockIdx.x * blockDim.x + threadIdx.x;
    const float* src; __nv_bfloat16 *dh, *dl; size_t off;
    if (i4 < 196608)      { src = lW;  dh = g_pWH;           dl = g_pWL;           off = i4; }
    else if (i4 < 393216) { src = rW;  dh = g_pWH + 786432;  dl = g_pWL + 786432;  off = i4 - 196608; }
    else if (i4 < 655360) { src = lhw; dh = g_hWH;           dl = g_hWL;           off = i4 - 393216; }
    else if (i4 < 917504) { src = rhw; dh = g_hWH + 1048576; dl = g_hWL + 1048576; off = i4 - 655360; }
    else return;
    float4 v = ((const float4*)src)[off];
    ushort4 hv, lv;
    split2(v.x, hv.x, lv.x); split2(v.y, hv.y, lv.y);
    split2(v.z, hv.z, lv.z); split2(v.w, hv.w, lv.w);
    ((ushort4*)dh)[off] = hv;
    ((ushort4*)dl)[off] = lv;
}

// ------------------------------------------------- shared GEMM micro-kernel
__device__ __forceinline__ void compute_chunk(uint32_t sb, int st, int lane,
                                              int mbase, int nbase,
                                              float acc[2][8][4]) {
    uint32_t aH = sb + (uint32_t)st * STAGE;
    uint32_t aL = aH + TERM;
    uint32_t bH = aH + 2 * TERM;
    uint32_t bL = aH + 3 * TERM;
    #pragma unroll
    for (int ks = 0; ks < 2; ++ks) {
        uint32_t Ahf[2][4], Alf[2][4], Bhf[8][2], Blf[8][2];
        uint32_t aoff = (uint32_t)(mbase + (lane & 15)) * ROWB +
                        (uint32_t)(ks * 32 + ((lane >> 4) << 4));
        #pragma unroll
        for (int i = 0; i < 2; ++i) {
            uint32_t ad = aoff + (uint32_t)(i * 16) * ROWB;
            ldsm4(Ahf[i][0], Ahf[i][1], Ahf[i][2], Ahf[i][3], aH + ad);
            ldsm4(Alf[i][0], Alf[i][1], Alf[i][2], Alf[i][3], aL + ad);
        }
        uint32_t boff = (uint32_t)(nbase + ((lane >> 4) & 1) * 8 + (lane & 7)) * ROWB +
                        (uint32_t)(ks * 32 + ((lane >> 3) & 1) * 16);
        #pragma unroll
        for (int jp = 0; jp < 4; ++jp) {
            uint32_t bd = boff + (uint32_t)(jp * 16) * ROWB;
            ldsm4(Bhf[jp*2][0], Bhf[jp*2][1], Bhf[jp*2+1][0], Bhf[jp*2+1][1], bH + bd);
            ldsm4(Blf[jp*2][0], Blf[jp*2][1], Blf[jp*2+1][0], Blf[jp*2+1][1], bL + bd);
        }
        #pragma unroll
        for (int i = 0; i < 2; ++i)
            #pragma unroll
            for (int j = 0; j < 8; ++j) {
                mma16816(acc[i][j], Ahf[i], Bhf[j]);
                mma16816(acc[i][j], Alf[i], Bhf[j]);
                mma16816(acc[i][j], Ahf[i], Blf[j]);
            }
    }
}

// Store accumulators to SMEM fp32 [128][132]
__device__ __forceinline__ void acc_to_smem(float* sv, int lane, int mbase, int nbase,
                                            float acc[2][8][4]) {
    #pragma unroll
    for (int i = 0; i < 2; ++i)
        #pragma unroll
        for (int j = 0; j < 8; ++j) {
            int r = mbase + i * 16 + (lane >> 2);
            int c = nbase + j * 8 + (lane & 3) * 2;
            sv[r * 132 + c]           = acc[i][j][0];
            sv[r * 132 + c + 1]       = acc[i][j][1];
            sv[(r + 8) * 132 + c]     = acc[i][j][2];
            sv[(r + 8) * 132 + c + 1] = acc[i][j][3];
        }
}

// ---------------------------------------------------------------- proj GEMM
__global__ __launch_bounds__(256) void proj_mma(const float* __restrict__ lb,
                                                const float* __restrict__ rb) {
    extern __shared__ char smem[];
    uint32_t sb = s2u(smem);
    const int tid = threadIdx.x, lane = tid & 31, wid = tid >> 5;
    const int warp_m = wid & 3, warp_n = wid >> 2;
    const int mbase = warp_m * 32, nbase = warp_n * 64;
    const int side = blockIdx.z, h0 = blockIdx.y * 128, token0 = blockIdx.x * 128;
    const int b = token0 >> 9, t0 = token0 & 511;

    const __nv_bfloat16* Ah = g_padH + ((size_t)b * CSP + t0 + side * 2) * CD;
    const __nv_bfloat16* Al = g_padL + ((size_t)b * CSP + t0 + side * 2) * CD;
    const __nv_bfloat16* Wh = g_pWH + (size_t)side * CD * CIN;
    const __nv_bfloat16* Wl = g_pWL + (size_t)side * CD * CIN;

    float acc[2][8][4] = {};

    auto load_chunk = [&](int c, int st) {
        uint32_t base = sb + (uint32_t)st * STAGE;
        int kb = c * 32;
        int j = kb >> 9, d0 = kb & 511;
        const __nv_bfloat16* ah = Ah + (size_t)j * CD + d0;
        const __nv_bfloat16* al = Al + (size_t)j * CD + d0;
        #pragma unroll
        for (int t = 0; t < 2; ++t) {
            int ci = tid + t * 256, row = ci >> 2, cc = ci & 3;
            uint32_t so = (uint32_t)row * ROWB + cc * 16;
            cpa16(base + so,            ah + (size_t)row * CD + cc * 8);
            cpa16(base + TERM + so,     al + (size_t)row * CD + cc * 8);
            cpa16(base + 2*TERM + so,   Wh + (size_t)(h0 + row) * CIN + kb + cc * 8);
            cpa16(base + 3*TERM + so,   Wl + (size_t)(h0 + row) * CIN + kb + cc * 8);
        }
        asm volatile("cp.async.commit_group;" ::: "memory");
    };

    const int C = CIN / 32;                         // 48
    load_chunk(0, 0);
    load_chunk(1, 1);
    int st = 0, ld = 2;                             // ld = next stage to fill
    for (int c = 0; c < C; ++c) {
        if (c + 1 < C) asm volatile("cp.async.wait_group 1;" ::: "memory");
        else           asm volatile("cp.async.wait_group 0;" ::: "memory");
        __syncthreads();                            // chunk c visible; compute(c-1) retired
        if (c + 2 < C) {
            load_chunk(c + 2, ld);
            if (++ld == NSTG) ld = 0;
        }
        compute_chunk(sb, st, lane, mbase, nbase, acc);
        if (++st == NSTG) st = 0;
    }
    __syncthreads();

    // epilogue: bias + relu + split, coalesced via SMEM
    float* sv = (float*)smem;
    acc_to_smem(sv, lane, mbase, nbase, acc);
    __syncthreads();
    const float* bias = side ? rb : lb;
    int row = tid >> 1, colb = (tid & 1) * 64;
    #pragma unroll
    for (int c4 = 0; c4 < 16; ++c4) {
        int col = colb + c4 * 4;
        ushort4 hv, lv;
        float v0 = fmaxf(sv[row * 132 + col + 0] + bias[h0 + col + 0], 0.f);
        float v1 = fmaxf(sv[row * 132 + col + 1] + bias[h0 + col + 1], 0.f);
        float v2 = fmaxf(sv[row * 132 + col + 2] + bias[h0 + col + 2], 0.f);
        float v3 = fmaxf(sv[row * 132 + col + 3] + bias[h0 + col + 3], 0.f);
        split2(v0, hv.x, lv.x); split2(v1, hv.y, lv.y);
        split2(v2, hv.z, lv.z); split2(v3, hv.w, lv.w);
        size_t o = ((size_t)side * CM + token0 + row) * CD + h0 + col;
        *(ushort4*)(g_a0H + o) = hv;
        *(ushort4*)(g_a0L + o) = lv;
    }
}

// ---------------------------------------------------------------- highway GEMM
// B rows 0-63 -> nonlin e=h0+r ; rows 64-127 -> gate e=512+h0+(r-64)
__global__ __launch_bounds__(256) void hw_mma(const __nv_bfloat16* __restrict__ inH,
                                              const __nv_bfloat16* __restrict__ inL,
                                              __nv_bfloat16* __restrict__ outH,
                                              __nv_bfloat16* __restrict__ outL,
                                              const float* __restrict__ lhwb,
                                              const float* __restrict__ rhwb,
                                              int layer, float* __restrict__ out, int dup) {
    extern __shared__ char smem[];
    uint32_t sb = s2u(smem);
    const int tid = threadIdx.x, lane = tid & 31, wid = tid >> 5;
    const int warp_m = wid & 3, warp_n = wid >> 2;
    const int mbase = warp_m * 32, nbase = warp_n * 64;
    const int side = blockIdx.z, h0 = blockIdx.y * 64, token0 = blockIdx.x * 128;

    const __nv_bfloat16* Ah = inH + ((size_t)side * CM + token0) * CD;
    const __nv_bfloat16* Al = inL + ((size_t)side * CM + token0) * CD;
    const __nv_bfloat16* Wh = g_hWH + ((size_t)side * 2 + layer) * 1024 * CD;
    const __nv_bfloat16* Wl = g_hWL + ((size_t)side * 2 + layer) * 1024 * CD;

    float acc[2][8][4] = {};

    auto load_chunk = [&](int c, int st) {
        uint32_t base = sb + (uint32_t)st * STAGE;
        int kb = c * 32;
        #pragma unroll
        for (int t = 0; t < 2; ++t) {
            int ci = tid + t * 256, row = ci >> 2, cc = ci & 3;
            int e = (row < 64) ? (h0 + row) : (448 + h0 + row);
            uint32_t so = (uint32_t)row * ROWB + cc * 16;
            cpa16(base + so,            Ah + (size_t)row * CD + kb + cc * 8);
            cpa16(base + TERM + so,     Al + (size_t)row * CD + kb + cc * 8);
            cpa16(base + 2*TERM + so,   Wh + (size_t)e * CD + kb + cc * 8);
            cpa16(base + 3*TERM + so,   Wl + (size_t)e * CD + kb + cc * 8);
        }
        asm volatile("cp.async.commit_group;" ::: "memory");
    };

    const int C = CD / 32;                          // 16
    load_chunk(0, 0);
    load_chunk(1, 1);
    int st = 0, ld = 2;
    for (int c = 0; c < C; ++c) {
        if (c + 1 < C) asm volatile("cp.async.wait_group 1;" ::: "memory");
        else           asm volatile("cp.async.wait_group 0;" ::: "memory");
        __syncthreads();
        if (c + 2 < C) {
            load_chunk(c + 2, ld);
            if (++ld == NSTG) ld = 0;
        }
        compute_chunk(sb, st, lane, mbase, nbase, acc);
        if (++st == NSTG) st = 0;
    }
    __syncthreads();

    // epilogue: gate, coalesced via SMEM; cols 0-63 nonlin, 64-127 gate
    float* sv = (float*)smem;
    acc_to_smem(sv, lane, mbase, nbase, acc);
    __syncthreads();
    const float* bias = (side ? rhwb : lhwb) + (size_t)layer * 1024;
    int row = tid >> 1, half = tid & 1;
    #pragma unroll
    for (int c4 = 0; c4 < 8; ++c4) {
        int col = half * 32 + c4 * 4;
        size_t o = ((size_t)side * CM + token0 + row) * CD + h0 + col;
        ushort4 xh = *(const ushort4*)(inH + o);
        ushort4 xl = *(const ushort4*)(inL + o);
        float x[4] = { bf2sum(xh.x, xl.x), bf2sum(xh.y, xl.y),
                       bf2sum(xh.z, xl.z), bf2sum(xh.w, xl.w) };
        float v[4];
        #pragma unroll
        for (int i = 0; i < 4; ++i) {
            float nl = fmaxf(sv[row * 132 + col + i] + bias[h0 + col + i], 0.f);
            float g  = 1.f / (1.f + expf(-(sv[row * 132 + col + 64 + i] +
                                           bias[512 + h0 + col + i])));
            v[i] = g * x[i] + (1.f - g) * nl;
        }
        if (out) {
            size_t oo = (size_t)(token0 + row) * 1024 + (size_t)side * 512 + h0 + col;
            *(float4*)(out + oo) = make_float4(v[0], v[1], v[2], v[3]);
            if (dup) *(float4*)(out + NOUT + oo) = make_float4(v[0], v[1], v[2], v[3]);
        } else {
            ushort4 hv, lv;
            split2(v[0], hv.x, lv.x); split2(v[1], hv.y, lv.y);
            split2(v[2], hv.z, lv.z); split2(v[3], hv.w, lv.w);
            *(ushort4*)(outH + o) = hv;
            *(ushort4*)(outL + o) = lv;
        }
    }
}

// ---------------------------------------------------------------- launcher
extern "C" void kernel_launch(void* const* d_in, const int* in_sizes, int n_in,
                              void* d_out, int out_size) {
    const float* inputs = (const float*)d_in[0];
    const float* lpad   = (const float*)d_in[1];
    const float* rpad   = (const float*)d_in[2];
    const float* lW     = (const float*)d_in[3];
    const float* lb     = (const float*)d_in[4];
    const float* rW     = (const float*)d_in[5];
    const float* rb     = (const float*)d_in[6];
    const float* lhwW   = (const float*)d_in[7];
    const float* lhwb   = (const float*)d_in[8];
    const float* rhwW   = (const float*)d_in[9];
    const float* rhwb   = (const float*)d_in[10];
    float* out = (float*)d_out;
    int dup = (out_size >= 2 * NOUT) ? 1 : 0;

    cudaFuncSetAttribute(proj_mma, cudaFuncAttributeMaxDynamicSharedMemorySize, SMEM_SZ);
    cudaFuncSetAttribute(hw_mma,   cudaFuncAttributeMaxDynamicSharedMemorySize, SMEM_SZ);

    __nv_bfloat16 *a0H, *a0L, *a1H, *a1L;
    cudaGetSymbolAddress((void**)&a0H, g_a0H);
    cudaGetSymbolAddress((void**)&a0L, g_a0L);
    cudaGetSymbolAddress((void**)&a1H, g_a1H);
    cudaGetSymbolAddress((void**)&a1L, g_a1L);

    pad_cvt<<<(CB * CSP * (CD / 4) + 255) / 256, 256>>>(inputs, lpad, rpad);
    wcvt<<<(917504 + 255) / 256, 256>>>(lW, rW, lhwW, rhwW);
    proj_mma<<<dim3(CM / 128, 4, 2), 256, SMEM_SZ>>>(lb, rb);
    hw_mma<<<dim3(CM / 128, 8, 2), 256, SMEM_SZ>>>(a0H, a0L, a1H, a1L,
                                                   lhwb, rhwb, 0, nullptr, 0);
    hw_mma<<<dim3(CM / 128, 8, 2), 256, SMEM_SZ>>>(a1H, a1L, nullptr, nullptr,
                                                   lhwb, rhwb, 1, out, dup);
}

// round 5
// speedup vs baseline: 1.3978x; 1.3978x over previous
#include <cuda_runtime.h>
#include <cuda_bf16.h>
#include <stdint.h>
#include <math.h>

// ---------------------------------------------------------------- constants
constexpr int CB = 32, CS = 512, CD = 512;
constexpr int CSP = CS + 4;
constexpr int CIN = 3 * CD;          // 1536
constexpr int CM  = CB * CS;         // 16384
constexpr int NOUT = CM * 2 * CD;

// ------------------------------------------------- device scratch (no alloc)
__device__ __nv_bfloat16 g_padH[(size_t)CB * CSP * CD];
__device__ __nv_bfloat16 g_padL[(size_t)CB * CSP * CD];
__device__ __nv_bfloat16 g_pWH[(size_t)2 * CD * CIN];
__device__ __nv_bfloat16 g_pWL[(size_t)2 * CD * CIN];
__device__ __nv_bfloat16 g_hWH[(size_t)2 * 2 * 1024 * CD];
__device__ __nv_bfloat16 g_hWL[(size_t)2 * 2 * 1024 * CD];
__device__ __nv_bfloat16 g_a0H[(size_t)2 * CM * CD];
__device__ __nv_bfloat16 g_a0L[(size_t)2 * CM * CD];
__device__ __nv_bfloat16 g_a1H[(size_t)2 * CM * CD];
__device__ __nv_bfloat16 g_a1L[(size_t)2 * CM * CD];

// SMEM tile geometry: packed 64 B rows, XOR-swizzled 16B slots (conflict-free)
constexpr uint32_t TERM  = 128 * 64;         // 8192 B per term tile
constexpr uint32_t STAGE = 4 * TERM;         // Ah|Al|Bh|Bl = 32768 B
constexpr int      NSTG  = 3;
constexpr uint32_t SMEM_SZ = NSTG * STAGE;   // 98304 B  (2 CTAs/SM)

// swizzled byte offset of 16B slot b (0..3) in row r
__device__ __forceinline__ uint32_t soff(uint32_t r, uint32_t b) {
    return (r << 6) + (((b ^ ((r >> 1) & 3)) & 3) << 4);
}

// ---------------------------------------------------------------- PTX utils
__device__ __forceinline__ uint32_t s2u(const void* p) {
    return (uint32_t)__cvta_generic_to_shared(p);
}
__device__ __forceinline__ void cpa16(uint32_t dst, const void* src) {
    asm volatile("cp.async.cg.shared.global [%0], [%1], 16;" :: "r"(dst), "l"(src));
}
__device__ __forceinline__ void ldsm4(uint32_t& r0, uint32_t& r1, uint32_t& r2,
                                      uint32_t& r3, uint32_t addr) {
    asm volatile("ldmatrix.sync.aligned.m8n8.x4.shared.b16 {%0,%1,%2,%3}, [%4];"
                 : "=r"(r0), "=r"(r1), "=r"(r2), "=r"(r3) : "r"(addr));
}
__device__ __forceinline__ void mma16816(float* d, const uint32_t* a, const uint32_t* b) {
    asm volatile(
        "mma.sync.aligned.m16n8k16.row.col.f32.bf16.bf16.f32 "
        "{%0,%1,%2,%3}, {%4,%5,%6,%7}, {%8,%9}, {%0,%1,%2,%3};"
        : "+f"(d[0]), "+f"(d[1]), "+f"(d[2]), "+f"(d[3])
        : "r"(a[0]), "r"(a[1]), "r"(a[2]), "r"(a[3]), "r"(b[0]), "r"(b[1]));
}
__device__ __forceinline__ void split2(float x, unsigned short& h, unsigned short& l) {
    __nv_bfloat16 hb = __float2bfloat16(x);
    __nv_bfloat16 lb = __float2bfloat16(x - __bfloat162float(hb));
    h = __bfloat16_as_ushort(hb);
    l = __bfloat16_as_ushort(lb);
}
__device__ __forceinline__ float bf2sum(unsigned short h, unsigned short l) {
    return __bfloat162float(__ushort_as_bfloat16(h)) +
           __bfloat162float(__ushort_as_bfloat16(l));
}

// ---------------------------------------------------------------- kernel 1
__global__ void pad_cvt(const float* __restrict__ inp, const float* __restrict__ lp,
                        const float* __restrict__ rp) {
    int idx = blockIdx.x * blockDim.x + threadIdx.x;   // float4 units
    const int per_b = CSP * (CD / 4);
    if (idx >= CB * per_b) return;
    int b = idx / per_b, rem = idx - b * per_b;
    int row = rem >> 7, d4 = rem & 127;
    float4 v;
    if (row < 2)             v = ((const float4*)lp)[row * 128 + d4];
    else if (row >= CSP - 2) v = ((const float4*)rp)[(row - (CSP - 2)) * 128 + d4];
    else v = ((const float4*)inp)[((size_t)b * CS + (row - 2)) * 128 + d4];
    ushort4 hv, lv;
    split2(v.x, hv.x, lv.x); split2(v.y, hv.y, lv.y);
    split2(v.z, hv.z, lv.z); split2(v.w, hv.w, lv.w);
    ((ushort4*)g_padH)[idx] = hv;
    ((ushort4*)g_padL)[idx] = lv;
}

// ---------------------------------------------------------------- kernel 2
__global__ void wcvt(const float* __restrict__ lW, const float* __restrict__ rW,
                     const float* __restrict__ lhw, const float* __restrict__ rhw) {
    int i4 = blockIdx.x * blockDim.x + threadIdx.x;
    const float* src; __nv_bfloat16 *dh, *dl; size_t off;
    if (i4 < 196608)      { src = lW;  dh = g_pWH;           dl = g_pWL;           off = i4; }
    else if (i4 < 393216) { src = rW;  dh = g_pWH + 786432;  dl = g_pWL + 786432;  off = i4 - 196608; }
    else if (i4 < 655360) { src = lhw; dh = g_hWH;           dl = g_hWL;           off = i4 - 393216; }
    else if (i4 < 917504) { src = rhw; dh = g_hWH + 1048576; dl = g_hWL + 1048576; off = i4 - 655360; }
    else return;
    float4 v = ((const float4*)src)[off];
    ushort4 hv, lv;
    split2(v.x, hv.x, lv.x); split2(v.y, hv.y, lv.y);
    split2(v.z, hv.z, lv.z); split2(v.w, hv.w, lv.w);
    ((ushort4*)dh)[off] = hv;
    ((ushort4*)dl)[off] = lv;
}

// ------------------------------------------------- shared GEMM micro-kernel
__device__ __forceinline__ void compute_chunk(uint32_t sb, int st, int lane,
                                              int mbase, int nbase,
                                              float acc[2][8][4]) {
    uint32_t aH = sb + (uint32_t)st * STAGE;
    uint32_t aL = aH + TERM;
    uint32_t bH = aH + 2 * TERM;
    uint32_t bL = aH + 3 * TERM;
    #pragma unroll
    for (int ks = 0; ks < 2; ++ks) {
        uint32_t Ahf[2][4], Alf[2][4], Bhf[8][2], Blf[8][2];
        // A rows: mbase + i*16 + (lane&15); slot b = ks*2 + (lane>>4)
        uint32_t ab = (uint32_t)(ks * 2 + (lane >> 4));
        #pragma unroll
        for (int i = 0; i < 2; ++i) {
            uint32_t r = (uint32_t)(mbase + i * 16 + (lane & 15));
            uint32_t ad = soff(r, ab);
            ldsm4(Ahf[i][0], Ahf[i][1], Ahf[i][2], Ahf[i][3], aH + ad);
            ldsm4(Alf[i][0], Alf[i][1], Alf[i][2], Alf[i][3], aL + ad);
        }
        // B rows: nbase + jp*16 + ((lane>>4)&1)*8 + (lane&7); slot b = ks*2 + ((lane>>3)&1)
        uint32_t bb = (uint32_t)(ks * 2 + ((lane >> 3) & 1));
        uint32_t brow = (uint32_t)(nbase + ((lane >> 4) & 1) * 8 + (lane & 7));
        #pragma unroll
        for (int jp = 0; jp < 4; ++jp) {
            uint32_t bd = soff(brow + jp * 16, bb);
            ldsm4(Bhf[jp*2][0], Bhf[jp*2][1], Bhf[jp*2+1][0], Bhf[jp*2+1][1], bH + bd);
            ldsm4(Blf[jp*2][0], Blf[jp*2][1], Blf[jp*2+1][0], Blf[jp*2+1][1], bL + bd);
        }
        #pragma unroll
        for (int i = 0; i < 2; ++i)
            #pragma unroll
            for (int j = 0; j < 8; ++j) {
                mma16816(acc[i][j], Ahf[i], Bhf[j]);
                mma16816(acc[i][j], Alf[i], Bhf[j]);
                mma16816(acc[i][j], Ahf[i], Blf[j]);
            }
    }
}

// Store accumulators to SMEM fp32 [128][132]
__device__ __forceinline__ void acc_to_smem(float* sv, int lane, int mbase, int nbase,
                                            float acc[2][8][4]) {
    #pragma unroll
    for (int i = 0; i < 2; ++i)
        #pragma unroll
        for (int j = 0; j < 8; ++j) {
            int r = mbase + i * 16 + (lane >> 2);
            int c = nbase + j * 8 + (lane & 3) * 2;
            sv[r * 132 + c]           = acc[i][j][0];
            sv[r * 132 + c + 1]       = acc[i][j][1];
            sv[(r + 8) * 132 + c]     = acc[i][j][2];
            sv[(r + 8) * 132 + c + 1] = acc[i][j][3];
        }
}

// ---------------------------------------------------------------- proj GEMM
__global__ __launch_bounds__(256, 2) void proj_mma(const float* __restrict__ lb,
                                                   const float* __restrict__ rb) {
    extern __shared__ char smem[];
    uint32_t sb = s2u(smem);
    const int tid = threadIdx.x, lane = tid & 31, wid = tid >> 5;
    const int warp_m = wid & 3, warp_n = wid >> 2;
    const int mbase = warp_m * 32, nbase = warp_n * 64;
    const int side = blockIdx.z, h0 = blockIdx.y * 128, token0 = blockIdx.x * 128;
    const int b = token0 >> 9, t0 = token0 & 511;

    const __nv_bfloat16* Ah = g_padH + ((size_t)b * CSP + t0 + side * 2) * CD;
    const __nv_bfloat16* Al = g_padL + ((size_t)b * CSP + t0 + side * 2) * CD;
    const __nv_bfloat16* Wh = g_pWH + (size_t)side * CD * CIN;
    const __nv_bfloat16* Wl = g_pWL + (size_t)side * CD * CIN;

    float acc[2][8][4] = {};

    auto load_chunk = [&](int c, int st) {
        uint32_t base = sb + (uint32_t)st * STAGE;
        int kb = c * 32;
        int j = kb >> 9, d0 = kb & 511;
        const __nv_bfloat16* ah = Ah + (size_t)j * CD + d0;
        const __nv_bfloat16* al = Al + (size_t)j * CD + d0;
        #pragma unroll
        for (int t = 0; t < 2; ++t) {
            int ci = tid + t * 256;
            uint32_t row = (uint32_t)(ci >> 2), bslot = (uint32_t)(ci & 3);
            uint32_t so = soff(row, bslot);
            cpa16(base + so,            ah + (size_t)row * CD + bslot * 8);
            cpa16(base + TERM + so,     al + (size_t)row * CD + bslot * 8);
            cpa16(base + 2*TERM + so,   Wh + (size_t)(h0 + row) * CIN + kb + bslot * 8);
            cpa16(base + 3*TERM + so,   Wl + (size_t)(h0 + row) * CIN + kb + bslot * 8);
        }
        asm volatile("cp.async.commit_group;" ::: "memory");
    };

    const int C = CIN / 32;                         // 48
    load_chunk(0, 0);
    load_chunk(1, 1);
    int st = 0, ld = 2;                             // ld = next stage to fill
    for (int c = 0; c < C; ++c) {
        if (c + 1 < C) asm volatile("cp.async.wait_group 1;" ::: "memory");
        else           asm volatile("cp.async.wait_group 0;" ::: "memory");
        __syncthreads();                            // chunk c visible; compute(c-1) retired
        if (c + 2 < C) {
            load_chunk(c + 2, ld);
            if (++ld == NSTG) ld = 0;
        }
        compute_chunk(sb, st, lane, mbase, nbase, acc);
        if (++st == NSTG) st = 0;
    }
    __syncthreads();

    // epilogue: bias + relu + split, coalesced via SMEM
    float* sv = (float*)smem;
    acc_to_smem(sv, lane, mbase, nbase, acc);
    __syncthreads();
    const float* bias = side ? rb : lb;
    int row = tid >> 1, colb = (tid & 1) * 64;
    #pragma unroll
    for (int c4 = 0; c4 < 16; ++c4) {
        int col = colb + c4 * 4;
        ushort4 hv, lv;
        float v0 = fmaxf(sv[row * 132 + col + 0] + bias[h0 + col + 0], 0.f);
        float v1 = fmaxf(sv[row * 132 + col + 1] + bias[h0 + col + 1], 0.f);
        float v2 = fmaxf(sv[row * 132 + col + 2] + bias[h0 + col + 2], 0.f);
        float v3 = fmaxf(sv[row * 132 + col + 3] + bias[h0 + col + 3], 0.f);
        split2(v0, hv.x, lv.x); split2(v1, hv.y, lv.y);
        split2(v2, hv.z, lv.z); split2(v3, hv.w, lv.w);
        size_t o = ((size_t)side * CM + token0 + row) * CD + h0 + col;
        *(ushort4*)(g_a0H + o) = hv;
        *(ushort4*)(g_a0L + o) = lv;
    }
}

// ---------------------------------------------------------------- highway GEMM
// B rows 0-63 -> nonlin e=h0+r ; rows 64-127 -> gate e=512+h0+(r-64)
__global__ __launch_bounds__(256, 2) void hw_mma(const __nv_bfloat16* __restrict__ inH,
                                                 const __nv_bfloat16* __restrict__ inL,
                                                 __nv_bfloat16* __restrict__ outH,
                                                 __nv_bfloat16* __restrict__ outL,
                                                 const float* __restrict__ lhwb,
                                                 const float* __restrict__ rhwb,
                                                 int layer, float* __restrict__ out, int dup) {
    extern __shared__ char smem[];
    uint32_t sb = s2u(smem);
    const int tid = threadIdx.x, lane = tid & 31, wid = tid >> 5;
    const int warp_m = wid & 3, warp_n = wid >> 2;
    const int mbase = warp_m * 32, nbase = warp_n * 64;
    const int side = blockIdx.z, h0 = blockIdx.y * 64, token0 = blockIdx.x * 128;

    const __nv_bfloat16* Ah = inH + ((size_t)side * CM + token0) * CD;
    const __nv_bfloat16* Al = inL + ((size_t)side * CM + token0) * CD;
    const __nv_bfloat16* Wh = g_hWH + ((size_t)side * 2 + layer) * 1024 * CD;
    const __nv_bfloat16* Wl = g_hWL + ((size_t)side * 2 + layer) * 1024 * CD;

    float acc[2][8][4] = {};

    auto load_chunk = [&](int c, int st) {
        uint32_t base = sb + (uint32_t)st * STAGE;
        int kb = c * 32;
        #pragma unroll
        for (int t = 0; t < 2; ++t) {
            int ci = tid + t * 256;
            uint32_t row = (uint32_t)(ci >> 2), bslot = (uint32_t)(ci & 3);
            int e = (row < 64) ? (h0 + (int)row) : (448 + h0 + (int)row);
            uint32_t so = soff(row, bslot);
            cpa16(base + so,            Ah + (size_t)row * CD + kb + bslot * 8);
            cpa16(base + TERM + so,     Al + (size_t)row * CD + kb + bslot * 8);
            cpa16(base + 2*TERM + so,   Wh + (size_t)e * CD + kb + bslot * 8);
            cpa16(base + 3*TERM + so,   Wl + (size_t)e * CD + kb + bslot * 8);
        }
        asm volatile("cp.async.commit_group;" ::: "memory");
    };

    const int C = CD / 32;                          // 16
    load_chunk(0, 0);
    load_chunk(1, 1);
    int st = 0, ld = 2;
    for (int c = 0; c < C; ++c) {
        if (c + 1 < C) asm volatile("cp.async.wait_group 1;" ::: "memory");
        else           asm volatile("cp.async.wait_group 0;" ::: "memory");
        __syncthreads();
        if (c + 2 < C) {
            load_chunk(c + 2, ld);
            if (++ld == NSTG) ld = 0;
        }
        compute_chunk(sb, st, lane, mbase, nbase, acc);
        if (++st == NSTG) st = 0;
    }
    __syncthreads();

    // epilogue: gate, coalesced via SMEM; cols 0-63 nonlin, 64-127 gate
    float* sv = (float*)smem;
    acc_to_smem(sv, lane, mbase, nbase, acc);
    __syncthreads();
    const float* bias = (side ? rhwb : lhwb) + (size_t)layer * 1024;
    int row = tid >> 1, half = tid & 1;
    #pragma unroll
    for (int c4 = 0; c4 < 8; ++c4) {
        int col = half * 32 + c4 * 4;
        size_t o = ((size_t)side * CM + token0 + row) * CD + h0 + col;
        ushort4 xh = *(const ushort4*)(inH + o);
        ushort4 xl = *(const ushort4*)(inL + o);
        float x[4] = { bf2sum(xh.x, xl.x), bf2sum(xh.y, xl.y),
                       bf2sum(xh.z, xl.z), bf2sum(xh.w, xl.w) };
        float v[4];
        #pragma unroll
        for (int i = 0; i < 4; ++i) {
            float nl = fmaxf(sv[row * 132 + col + i] + bias[h0 + col + i], 0.f);
            float g  = 1.f / (1.f + expf(-(sv[row * 132 + col + 64 + i] +
                                           bias[512 + h0 + col + i])));
            v[i] = g * x[i] + (1.f - g) * nl;
        }
        if (out) {
            size_t oo = (size_t)(token0 + row) * 1024 + (size_t)side * 512 + h0 + col;
            *(float4*)(out + oo) = make_float4(v[0], v[1], v[2], v[3]);
            if (dup) *(float4*)(out + NOUT + oo) = make_float4(v[0], v[1], v[2], v[3]);
        } else {
            ushort4 hv, lv;
            split2(v[0], hv.x, lv.x); split2(v[1], hv.y, lv.y);
            split2(v[2], hv.z, lv.z); split2(v[3], hv.w, lv.w);
            *(ushort4*)(outH + o) = hv;
            *(ushort4*)(outL + o) = lv;
        }
    }
}

// ---------------------------------------------------------------- launcher
extern "C" void kernel_launch(void* const* d_in, const int* in_sizes, int n_in,
                              void* d_out, int out_size) {
    const float* inputs = (const float*)d_in[0];
    const float* lpad   = (const float*)d_in[1];
    const float* rpad   = (const float*)d_in[2];
    const float* lW     = (const float*)d_in[3];
    const float* lb     = (const float*)d_in[4];
    const float* rW     = (const float*)d_in[5];
    const float* rb     = (const float*)d_in[6];
    const float* lhwW   = (const float*)d_in[7];
    const float* lhwb   = (const float*)d_in[8];
    const float* rhwW   = (const float*)d_in[9];
    const float* rhwb   = (const float*)d_in[10];
    float* out = (float*)d_out;
    int dup = (out_size >= 2 * NOUT) ? 1 : 0;

    cudaFuncSetAttribute(proj_mma, cudaFuncAttributeMaxDynamicSharedMemorySize, SMEM_SZ);
    cudaFuncSetAttribute(hw_mma,   cudaFuncAttributeMaxDynamicSharedMemorySize, SMEM_SZ);

    __nv_bfloat16 *a0H, *a0L, *a1H, *a1L;
    cudaGetSymbolAddress((void**)&a0H, g_a0H);
    cudaGetSymbolAddress((void**)&a0L, g_a0L);
    cudaGetSymbolAddress((void**)&a1H, g_a1H);
    cudaGetSymbolAddress((void**)&a1L, g_a1L);

    pad_cvt<<<(CB * CSP * (CD / 4) + 255) / 256, 256>>>(inputs, lpad, rpad);
    wcvt<<<(917504 + 255) / 256, 256>>>(lW, rW, lhwW, rhwW);
    proj_mma<<<dim3(CM / 128, 4, 2), 256, SMEM_SZ>>>(lb, rb);
    hw_mma<<<dim3(CM / 128, 8, 2), 256, SMEM_SZ>>>(a0H, a0L, a1H, a1L,
                                                   lhwb, rhwb, 0, nullptr, 0);
    hw_mma<<<dim3(CM / 128, 8, 2), 256, SMEM_SZ>>>(a1H, a1L, nullptr, nullptr,
                                                   lhwb, rhwb, 1, out, dup);
}

// round 6
// speedup vs baseline: 1.4753x; 1.0554x over previous
#include <cuda_runtime.h>
#include <cuda_bf16.h>
#include <stdint.h>
#include <math.h>

// ---------------------------------------------------------------- constants
constexpr int CB = 32, CS = 512, CD = 512;
constexpr int CSP = CS + 4;
constexpr int CIN = 3 * CD;          // 1536
constexpr int CM  = CB * CS;         // 16384
constexpr int NOUT = CM * 2 * CD;

// ------------------------------------------------- device scratch (no alloc)
__device__ __nv_bfloat16 g_padH[(size_t)CB * CSP * CD];
__device__ __nv_bfloat16 g_padL[(size_t)CB * CSP * CD];
__device__ __nv_bfloat16 g_pWH[(size_t)2 * CD * CIN];
__device__ __nv_bfloat16 g_pWL[(size_t)2 * CD * CIN];
__device__ __nv_bfloat16 g_hWH[(size_t)2 * 2 * 1024 * CD];
__device__ __nv_bfloat16 g_hWL[(size_t)2 * 2 * 1024 * CD];
__device__ __nv_bfloat16 g_a0H[(size_t)2 * CM * CD];
__device__ __nv_bfloat16 g_a0L[(size_t)2 * CM * CD];
__device__ __nv_bfloat16 g_a1H[(size_t)2 * CM * CD];
__device__ __nv_bfloat16 g_a1L[(size_t)2 * CM * CD];

// SMEM tile geometry: packed 64 B rows, XOR-swizzled 16B slots (conflict-free)
constexpr uint32_t TERM  = 128 * 64;         // 8192 B per term tile
constexpr uint32_t STAGE = 4 * TERM;         // Ah|Al|Bh|Bl = 32768 B
constexpr int      NSTG  = 3;
constexpr uint32_t SMEM_SZ = NSTG * STAGE;   // 98304 B  (2 CTAs/SM)

// swizzled byte offset of 16B slot b (0..3) in row r
__device__ __forceinline__ uint32_t soff(uint32_t r, uint32_t b) {
    return (r << 6) + (((b ^ ((r >> 1) & 3)) & 3) << 4);
}

// ---------------------------------------------------------------- PTX utils
__device__ __forceinline__ uint32_t s2u(const void* p) {
    return (uint32_t)__cvta_generic_to_shared(p);
}
__device__ __forceinline__ void cpa16(uint32_t dst, const void* src) {
    asm volatile("cp.async.cg.shared.global [%0], [%1], 16;" :: "r"(dst), "l"(src));
}
__device__ __forceinline__ void ldsm4(uint32_t& r0, uint32_t& r1, uint32_t& r2,
                                      uint32_t& r3, uint32_t addr) {
    asm volatile("ldmatrix.sync.aligned.m8n8.x4.shared.b16 {%0,%1,%2,%3}, [%4];"
                 : "=r"(r0), "=r"(r1), "=r"(r2), "=r"(r3) : "r"(addr));
}
__device__ __forceinline__ void mma16816(float* d, const uint32_t* a, const uint32_t* b) {
    asm volatile(
        "mma.sync.aligned.m16n8k16.row.col.f32.bf16.bf16.f32 "
        "{%0,%1,%2,%3}, {%4,%5,%6,%7}, {%8,%9}, {%0,%1,%2,%3};"
        : "+f"(d[0]), "+f"(d[1]), "+f"(d[2]), "+f"(d[3])
        : "r"(a[0]), "r"(a[1]), "r"(a[2]), "r"(a[3]), "r"(b[0]), "r"(b[1]));
}
__device__ __forceinline__ void split2(float x, unsigned short& h, unsigned short& l) {
    __nv_bfloat16 hb = __float2bfloat16(x);
    __nv_bfloat16 lb = __float2bfloat16(x - __bfloat162float(hb));
    h = __bfloat16_as_ushort(hb);
    l = __bfloat16_as_ushort(lb);
}
__device__ __forceinline__ float bf2sum(unsigned short h, unsigned short l) {
    return __bfloat162float(__ushort_as_bfloat16(h)) +
           __bfloat162float(__ushort_as_bfloat16(l));
}

// ---------------------------------------------------------------- kernel 1
__global__ void pad_cvt(const float* __restrict__ inp, const float* __restrict__ lp,
                        const float* __restrict__ rp) {
    int idx = blockIdx.x * blockDim.x + threadIdx.x;   // float4 units
    const int per_b = CSP * (CD / 4);
    if (idx >= CB * per_b) return;
    int b = idx / per_b, rem = idx - b * per_b;
    int row = rem >> 7, d4 = rem & 127;
    float4 v;
    if (row < 2)             v = ((const float4*)lp)[row * 128 + d4];
    else if (row >= CSP - 2) v = ((const float4*)rp)[(row - (CSP - 2)) * 128 + d4];
    else v = ((const float4*)inp)[((size_t)b * CS + (row - 2)) * 128 + d4];
    ushort4 hv, lv;
    split2(v.x, hv.x, lv.x); split2(v.y, hv.y, lv.y);
    split2(v.z, hv.z, lv.z); split2(v.w, hv.w, lv.w);
    ((ushort4*)g_padH)[idx] = hv;
    ((ushort4*)g_padL)[idx] = lv;
}

// ---------------------------------------------------------------- kernel 2
__global__ void wcvt(const float* __restrict__ lW, const float* __restrict__ rW,
                     const float* __restrict__ lhw, const float* __restrict__ rhw) {
    int i4 = blockIdx.x * blockDim.x + threadIdx.x;
    const float* src; __nv_bfloat16 *dh, *dl; size_t off;
    if (i4 < 196608)      { src = lW;  dh = g_pWH;           dl = g_pWL;           off = i4; }
    else if (i4 < 393216) { src = rW;  dh = g_pWH + 786432;  dl = g_pWL + 786432;  off = i4 - 196608; }
    else if (i4 < 655360) { src = lhw; dh = g_hWH;           dl = g_hWL;           off = i4 - 393216; }
    else if (i4 < 917504) { src = rhw; dh = g_hWH + 1048576; dl = g_hWL + 1048576; off = i4 - 655360; }
    else return;
    float4 v = ((const float4*)src)[off];
    ushort4 hv, lv;
    split2(v.x, hv.x, lv.x); split2(v.y, hv.y, lv.y);
    split2(v.z, hv.z, lv.z); split2(v.w, hv.w, lv.w);
    ((ushort4*)dh)[off] = hv;
    ((ushort4*)dl)[off] = lv;
}

// ------------------------------------------------- shared GEMM micro-kernel
// Term-major MMA order: same-accumulator reuse distance = 16 MMAs.
__device__ __forceinline__ void compute_chunk(uint32_t sb, int st, int lane,
                                              int mbase, int nbase,
                                              float acc[2][8][4]) {
    uint32_t aH = sb + (uint32_t)st * STAGE;
    uint32_t aL = aH + TERM;
    uint32_t bH = aH + 2 * TERM;
    uint32_t bL = aH + 3 * TERM;
    #pragma unroll
    for (int ks = 0; ks < 2; ++ks) {
        uint32_t Ahf[2][4], Alf[2][4], Bhf[8][2], Blf[8][2];
        uint32_t ab = (uint32_t)(ks * 2 + (lane >> 4));
        uint32_t bb = (uint32_t)(ks * 2 + ((lane >> 3) & 1));
        uint32_t brow = (uint32_t)(nbase + ((lane >> 4) & 1) * 8 + (lane & 7));
        // hi-term operands first so term0 can start ASAP
        #pragma unroll
        for (int i = 0; i < 2; ++i) {
            uint32_t ad = soff((uint32_t)(mbase + i * 16 + (lane & 15)), ab);
            ldsm4(Ahf[i][0], Ahf[i][1], Ahf[i][2], Ahf[i][3], aH + ad);
        }
        #pragma unroll
        for (int jp = 0; jp < 4; ++jp) {
            uint32_t bd = soff(brow + jp * 16, bb);
            ldsm4(Bhf[jp*2][0], Bhf[jp*2][1], Bhf[jp*2+1][0], Bhf[jp*2+1][1], bH + bd);
        }
        #pragma unroll
        for (int i = 0; i < 2; ++i) {
            uint32_t ad = soff((uint32_t)(mbase + i * 16 + (lane & 15)), ab);
            ldsm4(Alf[i][0], Alf[i][1], Alf[i][2], Alf[i][3], aL + ad);
        }
        #pragma unroll
        for (int jp = 0; jp < 4; ++jp) {
            uint32_t bd = soff(brow + jp * 16, bb);
            ldsm4(Blf[jp*2][0], Blf[jp*2][1], Blf[jp*2+1][0], Blf[jp*2+1][1], bL + bd);
        }
        // term 0: Ah * Bh
        #pragma unroll
        for (int i = 0; i < 2; ++i)
            #pragma unroll
            for (int j = 0; j < 8; ++j)
                mma16816(acc[i][j], Ahf[i], Bhf[j]);
        // term 1: Al * Bh
        #pragma unroll
        for (int i = 0; i < 2; ++i)
            #pragma unroll
            for (int j = 0; j < 8; ++j)
                mma16816(acc[i][j], Alf[i], Bhf[j]);
        // term 2: Ah * Bl
        #pragma unroll
        for (int i = 0; i < 2; ++i)
            #pragma unroll
            for (int j = 0; j < 8; ++j)
                mma16816(acc[i][j], Ahf[i], Blf[j]);
    }
}

// Store accumulators to SMEM fp32 [128][132]
__device__ __forceinline__ void acc_to_smem(float* sv, int lane, int mbase, int nbase,
                                            float acc[2][8][4]) {
    #pragma unroll
    for (int i = 0; i < 2; ++i)
        #pragma unroll
        for (int j = 0; j < 8; ++j) {
            int r = mbase + i * 16 + (lane >> 2);
            int c = nbase + j * 8 + (lane & 3) * 2;
            sv[r * 132 + c]           = acc[i][j][0];
            sv[r * 132 + c + 1]       = acc[i][j][1];
            sv[(r + 8) * 132 + c]     = acc[i][j][2];
            sv[(r + 8) * 132 + c + 1] = acc[i][j][3];
        }
}

// ---------------------------------------------------------------- proj GEMM
__global__ __launch_bounds__(256, 2) void proj_mma(const float* __restrict__ lb,
                                                   const float* __restrict__ rb) {
    extern __shared__ char smem[];
    uint32_t sb = s2u(smem);
    const int tid = threadIdx.x, lane = tid & 31, wid = tid >> 5;
    const int warp_m = wid & 3, warp_n = wid >> 2;
    const int mbase = warp_m * 32, nbase = warp_n * 64;
    const int side = blockIdx.z, h0 = blockIdx.y * 128, token0 = blockIdx.x * 128;
    const int b = token0 >> 9, t0 = token0 & 511;

    const __nv_bfloat16* Ah = g_padH + ((size_t)b * CSP + t0 + side * 2) * CD;
    const __nv_bfloat16* Al = g_padL + ((size_t)b * CSP + t0 + side * 2) * CD;
    const __nv_bfloat16* Wh = g_pWH + (size_t)side * CD * CIN;
    const __nv_bfloat16* Wl = g_pWL + (size_t)side * CD * CIN;

    float acc[2][8][4] = {};

    auto load_chunk = [&](int c, int st) {
        uint32_t base = sb + (uint32_t)st * STAGE;
        int kb = c * 32;
        int j = kb >> 9, d0 = kb & 511;
        const __nv_bfloat16* ah = Ah + (size_t)j * CD + d0;
        const __nv_bfloat16* al = Al + (size_t)j * CD + d0;
        #pragma unroll
        for (int t = 0; t < 2; ++t) {
            int ci = tid + t * 256;
            uint32_t row = (uint32_t)(ci >> 2), bslot = (uint32_t)(ci & 3);
            uint32_t so = soff(row, bslot);
            cpa16(base + so,            ah + (size_t)row * CD + bslot * 8);
            cpa16(base + TERM + so,     al + (size_t)row * CD + bslot * 8);
            cpa16(base + 2*TERM + so,   Wh + (size_t)(h0 + row) * CIN + kb + bslot * 8);
            cpa16(base + 3*TERM + so,   Wl + (size_t)(h0 + row) * CIN + kb + bslot * 8);
        }
        asm volatile("cp.async.commit_group;" ::: "memory");
    };

    const int C = CIN / 32;                         // 48
    load_chunk(0, 0);
    load_chunk(1, 1);
    int st = 0, ld = 2;                             // ld = next stage to fill
    for (int c = 0; c < C; ++c) {
        if (c + 1 < C) asm volatile("cp.async.wait_group 1;" ::: "memory");
        else           asm volatile("cp.async.wait_group 0;" ::: "memory");
        __syncthreads();                            // chunk c visible; compute(c-1) retired
        compute_chunk(sb, st, lane, mbase, nbase, acc);
        if (++st == NSTG) st = 0;
        if (c + 2 < C) {                            // issue after MMAs: pipe refills first
            load_chunk(c + 2, ld);
            if (++ld == NSTG) ld = 0;
        }
    }
    __syncthreads();

    // epilogue: bias + relu + split, coalesced via SMEM
    float* sv = (float*)smem;
    acc_to_smem(sv, lane, mbase, nbase, acc);
    __syncthreads();
    const float* bias = side ? rb : lb;
    int row = tid >> 1, colb = (tid & 1) * 64;
    #pragma unroll
    for (int c4 = 0; c4 < 16; ++c4) {
        int col = colb + c4 * 4;
        ushort4 hv, lv;
        float v0 = fmaxf(sv[row * 132 + col + 0] + bias[h0 + col + 0], 0.f);
        float v1 = fmaxf(sv[row * 132 + col + 1] + bias[h0 + col + 1], 0.f);
        float v2 = fmaxf(sv[row * 132 + col + 2] + bias[h0 + col + 2], 0.f);
        float v3 = fmaxf(sv[row * 132 + col + 3] + bias[h0 + col + 3], 0.f);
        split2(v0, hv.x, lv.x); split2(v1, hv.y, lv.y);
        split2(v2, hv.z, lv.z); split2(v3, hv.w, lv.w);
        size_t o = ((size_t)side * CM + token0 + row) * CD + h0 + col;
        *(ushort4*)(g_a0H + o) = hv;
        *(ushort4*)(g_a0L + o) = lv;
    }
}

// ---------------------------------------------------------------- highway GEMM
// B rows 0-63 -> nonlin e=h0+r ; rows 64-127 -> gate e=512+h0+(r-64)
__global__ __launch_bounds__(256, 2) void hw_mma(const __nv_bfloat16* __restrict__ inH,
                                                 const __nv_bfloat16* __restrict__ inL,
                                                 __nv_bfloat16* __restrict__ outH,
                                                 __nv_bfloat16* __restrict__ outL,
                                                 const float* __restrict__ lhwb,
                                                 const float* __restrict__ rhwb,
                                                 int layer, float* __restrict__ out, int dup) {
    extern __shared__ char smem[];
    uint32_t sb = s2u(smem);
    const int tid = threadIdx.x, lane = tid & 31, wid = tid >> 5;
    const int warp_m = wid & 3, warp_n = wid >> 2;
    const int mbase = warp_m * 32, nbase = warp_n * 64;
    const int side = blockIdx.z, h0 = blockIdx.y * 64, token0 = blockIdx.x * 128;

    const __nv_bfloat16* Ah = inH + ((size_t)side * CM + token0) * CD;
    const __nv_bfloat16* Al = inL + ((size_t)side * CM + token0) * CD;
    const __nv_bfloat16* Wh = g_hWH + ((size_t)side * 2 + layer) * 1024 * CD;
    const __nv_bfloat16* Wl = g_hWL + ((size_t)side * 2 + layer) * 1024 * CD;

    float acc[2][8][4] = {};

    auto load_chunk = [&](int c, int st) {
        uint32_t base = sb + (uint32_t)st * STAGE;
        int kb = c * 32;
        #pragma unroll
        for (int t = 0; t < 2; ++t) {
            int ci = tid + t * 256;
            uint32_t row = (uint32_t)(ci >> 2), bslot = (uint32_t)(ci & 3);
            int e = (row < 64) ? (h0 + (int)row) : (448 + h0 + (int)row);
            uint32_t so = soff(row, bslot);
            cpa16(base + so,            Ah + (size_t)row * CD + kb + bslot * 8);
            cpa16(base + TERM + so,     Al + (size_t)row * CD + kb + bslot * 8);
            cpa16(base + 2*TERM + so,   Wh + (size_t)e * CD + kb + bslot * 8);
            cpa16(base + 3*TERM + so,   Wl + (size_t)e * CD + kb + bslot * 8);
        }
        asm volatile("cp.async.commit_group;" ::: "memory");
    };

    const int C = CD / 32;                          // 16
    load_chunk(0, 0);
    load_chunk(1, 1);
    int st = 0, ld = 2;
    for (int c = 0; c < C; ++c) {
        if (c + 1 < C) asm volatile("cp.async.wait_group 1;" ::: "memory");
        else           asm volatile("cp.async.wait_group 0;" ::: "memory");
        __syncthreads();
        compute_chunk(sb, st, lane, mbase, nbase, acc);
        if (++st == NSTG) st = 0;
        if (c + 2 < C) {
            load_chunk(c + 2, ld);
            if (++ld == NSTG) ld = 0;
        }
    }
    __syncthreads();

    // epilogue: gate, coalesced via SMEM; cols 0-63 nonlin, 64-127 gate
    float* sv = (float*)smem;
    acc_to_smem(sv, lane, mbase, nbase, acc);
    __syncthreads();
    const float* bias = (side ? rhwb : lhwb) + (size_t)layer * 1024;
    int row = tid >> 1, half = tid & 1;
    #pragma unroll
    for (int c4 = 0; c4 < 8; ++c4) {
        int col = half * 32 + c4 * 4;
        size_t o = ((size_t)side * CM + token0 + row) * CD + h0 + col;
        ushort4 xh = *(const ushort4*)(inH + o);
        ushort4 xl = *(const ushort4*)(inL + o);
        float x[4] = { bf2sum(xh.x, xl.x), bf2sum(xh.y, xl.y),
                       bf2sum(xh.z, xl.z), bf2sum(xh.w, xl.w) };
        float v[4];
        #pragma unroll
        for (int i = 0; i < 4; ++i) {
            float nl = fmaxf(sv[row * 132 + col + i] + bias[h0 + col + i], 0.f);
            float g  = 1.f / (1.f + expf(-(sv[row * 132 + col + 64 + i] +
                                           bias[512 + h0 + col + i])));
            v[i] = g * x[i] + (1.f - g) * nl;
        }
        if (out) {
            size_t oo = (size_t)(token0 + row) * 1024 + (size_t)side * 512 + h0 + col;
            *(float4*)(out + oo) = make_float4(v[0], v[1], v[2], v[3]);
            if (dup) *(float4*)(out + NOUT + oo) = make_float4(v[0], v[1], v[2], v[3]);
        } else {
            ushort4 hv, lv;
            split2(v[0], hv.x, lv.x); split2(v[1], hv.y, lv.y);
            split2(v[2], hv.z, lv.z); split2(v[3], hv.w, lv.w);
            *(ushort4*)(outH + o) = hv;
            *(ushort4*)(outL + o) = lv;
        }
    }
}

// ---------------------------------------------------------------- launcher
extern "C" void kernel_launch(void* const* d_in, const int* in_sizes, int n_in,
                              void* d_out, int out_size) {
    const float* inputs = (const float*)d_in[0];
    const float* lpad   = (const float*)d_in[1];
    const float* rpad   = (const float*)d_in[2];
    const float* lW     = (const float*)d_in[3];
    const float* lb     = (const float*)d_in[4];
    const float* rW     = (const float*)d_in[5];
    const float* rb     = (const float*)d_in[6];
    const float* lhwW   = (const float*)d_in[7];
    const float* lhwb   = (const float*)d_in[8];
    const float* rhwW   = (const float*)d_in[9];
    const float* rhwb   = (const float*)d_in[10];
    float* out = (float*)d_out;
    int dup = (out_size >= 2 * NOUT) ? 1 : 0;

    cudaFuncSetAttribute(proj_mma, cudaFuncAttributeMaxDynamicSharedMemorySize, SMEM_SZ);
    cudaFuncSetAttribute(hw_mma,   cudaFuncAttributeMaxDynamicSharedMemorySize, SMEM_SZ);

    __nv_bfloat16 *a0H, *a0L, *a1H, *a1L;
    cudaGetSymbolAddress((void**)&a0H, g_a0H);
    cudaGetSymbolAddress((void**)&a0L, g_a0L);
    cudaGetSymbolAddress((void**)&a1H, g_a1H);
    cudaGetSymbolAddress((void**)&a1L, g_a1L);

    pad_cvt<<<(CB * CSP * (CD / 4) + 255) / 256, 256>>>(inputs, lpad, rpad);
    wcvt<<<(917504 + 255) / 256, 256>>>(lW, rW, lhwW, rhwW);
    proj_mma<<<dim3(CM / 128, 4, 2), 256, SMEM_SZ>>>(lb, rb);
    hw_mma<<<dim3(CM / 128, 8, 2), 256, SMEM_SZ>>>(a0H, a0L, a1H, a1L,
                                                   lhwb, rhwb, 0, nullptr, 0);
    hw_mma<<<dim3(CM / 128, 8, 2), 256, SMEM_SZ>>>(a1H, a1L, nullptr, nullptr,
                                                   lhwb, rhwb, 1, out, dup);
}